// round 3
// baseline (speedup 1.0000x reference)
#include <cuda_runtime.h>
#include <math.h>

// Problem constants (fixed by the dataset)
#define NPTS 65536
#define CH   128
#define NCLS 10
#define KNBR 27
#define OUTC 17   // 1 (ctr) + 6 (reg) + 10 (cls)

// sigmoid(s) > 0.15  <=>  s > log(0.15/0.85)
#define THRESH_LOGIT -1.7346010553881064f

#define G_BLOCKS   4096   // total blocks (all zero-fill)
#define SEM_BLOCKS 2048   // low block IDs also compute sem (32 points each)

// Scratch (__device__ globals, allocation-free). g_count/g_ticket are reset by
// the tail block at the END of each run, so every replay starts from 0.
__device__ int  g_count  = 0;
__device__ int  g_ticket = 0;
__device__ int2 g_pairs[NPTS * NCLS];

__device__ __forceinline__ float elu1(float x) {
    return x > 0.f ? x : (expf(x) - 1.f);
}

__global__ void __launch_bounds__(256, 2)
k_main(const float* __restrict__ feats,
       const int*   __restrict__ nbr,
       const float* __restrict__ Wsem,
       const float* __restrict__ bsem,
       const float* __restrict__ fo_w,
       const float* __restrict__ fo_g,
       const float* __restrict__ fo_b,
       const float* __restrict__ cls_out_w,
       const float* __restrict__ cls_out_g,
       const float* __restrict__ cls_out_b,
       const float* __restrict__ up_w,
       const float* __restrict__ up_g,
       const float* __restrict__ up_b,
       const float* __restrict__ fuse_w,
       const float* __restrict__ fuse_g,
       const float* __restrict__ fuse_b,
       const float* __restrict__ exp_w,
       const float* __restrict__ exp_g,
       const float* __restrict__ exp_b,
       const float* __restrict__ ctr_w,
       const float* __restrict__ reg_w,
       const float* __restrict__ cls_w,
       const float* __restrict__ cls_b,
       const float* __restrict__ scales,
       float* __restrict__ out,
       long long nelem, long long slice4) {
    __shared__ float4 sWt[NCLS * 32];     // Wsem transposed, float4 per (class, lanegroup)
    __shared__ float  sThr[NCLS];
    __shared__ int    s_tick;
    __shared__ int    s_np;
    // head-pipeline scratch (tail block only)
    __shared__ float sx[CH];
    __shared__ float cat[2 * CH];
    __shared__ float sec[CH];
    __shared__ float sof[CH];

    const int tid = threadIdx.x;
    const int b   = blockIdx.x;

    // ---------------- phase 1: zero-fill this block's output slice ----------
    {
        const long long n4 = nelem >> 2;
        float4* out4 = reinterpret_cast<float4*>(out);
        const float4 z = make_float4(0.f, 0.f, 0.f, 0.f);
        long long t   = (long long)b * slice4 + tid;
        long long end = (long long)(b + 1) * slice4;
        if (end > n4) end = n4;
        for (; t < end; t += 256) out4[t] = z;
        // scalar tail of nelem (nelem%4 == 0 for this problem; kept for safety)
        if (b == 0) {
            for (long long s = (n4 << 2) + tid; s < nelem; s += 256) out[s] = 0.f;
        }
    }

    // ---------------- phase 2: sem mask + pair compaction --------------------
    if (b < SEM_BLOCKS) {
        if (tid < NCLS * 32) {
            const int c = tid >> 5, g = tid & 31;
            sWt[tid] = make_float4(Wsem[(4 * g + 0) * NCLS + c],
                                   Wsem[(4 * g + 1) * NCLS + c],
                                   Wsem[(4 * g + 2) * NCLS + c],
                                   Wsem[(4 * g + 3) * NCLS + c]);
        }
        if (tid < NCLS) sThr[tid] = THRESH_LOGIT - bsem[tid];
        __syncthreads();

        const int warp = tid >> 5;
        const int lane = tid & 31;
        const int base = b * 32;

        // hoist weights into registers: reused for all 4 points of this warp
        float4 wr[NCLS];
#pragma unroll
        for (int c = 0; c < NCLS; c++) wr[c] = sWt[c * 32 + lane];

#pragma unroll
        for (int it = 0; it < 4; it++) {
            const int p = base + it * 8 + warp;
            const float4 f = reinterpret_cast<const float4*>(feats)[p * 32 + lane];
            float s[NCLS];
#pragma unroll
            for (int c = 0; c < NCLS; c++)
                s[c] = f.x * wr[c].x + f.y * wr[c].y + f.z * wr[c].z + f.w * wr[c].w;

            // folded reduction: xor16 on all 10, then split classes across the
            // two half-warps, butterfly xor8..1 on 5, then fetch lane16's set.
#pragma unroll
            for (int c = 0; c < NCLS; c++)
                s[c] += __shfl_xor_sync(0xffffffffu, s[c], 16);
            float t5[5];
            const bool hi = (lane >= 16);
#pragma unroll
            for (int k = 0; k < 5; k++) t5[k] = hi ? s[k + 5] : s[k];
#pragma unroll
            for (int off = 8; off; off >>= 1)
#pragma unroll
                for (int k = 0; k < 5; k++)
                    t5[k] += __shfl_xor_sync(0xffffffffu, t5[k], off);
            float u5[5];
#pragma unroll
            for (int k = 0; k < 5; k++)
                u5[k] = __shfl_sync(0xffffffffu, t5[k], 16);

            if (lane == 0) {
#pragma unroll
                for (int k = 0; k < 5; k++) {
                    if (t5[k] > sThr[k]) {
                        int pos = atomicAdd(&g_count, 1);
                        g_pairs[pos] = make_int2(k, p);
                    }
                    if (u5[k] > sThr[k + 5]) {
                        int pos = atomicAdd(&g_count, 1);
                        g_pairs[pos] = make_int2(k + 5, p);
                    }
                }
            }
        }
    }

    // ---------------- phase 3: ticket; last block runs the heads ------------
    __syncthreads();
    __threadfence();
    if (tid == 0) s_tick = atomicAdd(&g_ticket, 1);
    __syncthreads();
    if (s_tick != G_BLOCKS - 1) return;

    // tail block: all other blocks' writes are visible (fence before ticket)
    __threadfence();
    if (tid == 0) s_np = *(volatile int*)&g_count;
    __syncthreads();
    const int np = s_np;
    const int j = tid;   // channel for j<128

    for (int pp = 0; pp < np; pp++) {
        const int c = g_pairs[pp].x;
        const int i = g_pairs[pp].y;

        // offset_features[i] = ELU(affine(sum_k feats[nbr[i,k]] @ fo_w[k]))
        float acc = 0.f;
        for (int k = 0; k < KNBR; k++) {
            const int nb = nbr[i * KNBR + k];
            __syncthreads();
            if (j < CH) sx[j] = feats[(long long)nb * CH + j];
            __syncthreads();
            if (j < CH) {
                const float* W = fo_w + (long long)k * CH * CH;
                for (int m = 0; m < CH; m++) acc += sx[m] * W[m * CH + j];
            }
        }
        if (j < CH) sof[j] = elu1(acc * fo_g[j] + fo_b[j]);

        for (int half = 0; half < 2; half++) {
            __syncthreads();
            if (j < CH) sx[j] = (half == 0) ? sof[j] : feats[(long long)i * CH + j];
            __syncthreads();
            if (j < CH) {   // hc
                const float* W = cls_out_w + (long long)c * CH * CH;
                float a = 0.f;
                for (int m = 0; m < CH; m++) a += sx[m] * W[m * CH + j];
                a = a * cls_out_g[c * CH + j] + cls_out_b[c * CH + j];
                cat[j] = elu1(a);
            }
            __syncthreads();
            if (j < CH) {   // uc
                const float* W = up_w + (long long)c * CH * CH;
                float a = 0.f;
                for (int m = 0; m < CH; m++) a += cat[m] * W[m * CH + j];
                a = a * up_g[c * CH + j] + up_b[c * CH + j];
                cat[CH + j] = elu1(a);
            }
            __syncthreads();
            float fc = 0.f;
            if (j < CH) {   // fc
                const float* W = fuse_w + (long long)c * 2 * CH * CH;
                float a = 0.f;
                for (int m = 0; m < 2 * CH; m++) a += cat[m] * W[m * CH + j];
                a = a * fuse_g[c * CH + j] + fuse_b[c * CH + j];
                fc = elu1(a);
            }
            __syncthreads();
            if (j < CH) sx[j] = fc;
            __syncthreads();
            if (j < CH) {   // ec
                const float* W = exp_w + (long long)c * CH * CH;
                float a = 0.f;
                for (int m = 0; m < CH; m++) a += sx[m] * W[m * CH + j];
                a = a * exp_g[c * CH + j] + exp_b[c * CH + j];
                sec[j] = elu1(a);
            }
            __syncthreads();

            const long long row = (half == 0) ? (long long)i : (long long)(NPTS + i);
            float* orow = out + ((long long)c * 2 * NPTS + row) * OUTC;
            if (j == 0) {
                float s = 0.f;
                for (int m = 0; m < CH; m++) s += sec[m] * ctr_w[m];
                orow[0] = s;
            } else if (j < 7) {
                const int r = j - 1;
                float s = 0.f;
                for (int m = 0; m < CH; m++) s += sec[m] * reg_w[m * 6 + r];
                orow[j] = expf(scales[c] * s);
            } else if (j < 17) {
                const int q = j - 7;
                float s = 0.f;
                for (int m = 0; m < CH; m++) s += sec[m] * cls_w[m * NCLS + q];
                orow[j] = s + cls_b[q];
            }
        }
    }

    // reset scratch for the next replay (stream order guarantees safety)
    __syncthreads();
    if (tid == 0) {
        g_count  = 0;
        g_ticket = 0;
    }
}

// ---------------------------------------------------------------------------
// Launch. Input order per metadata: coords, feats, nbr, Wsem, bsem,
// off_w1,g1,b1, off_w2,g2,b2, off_w3, fo_w,g,b, cls_out_w,g,b, up_w,g,b,
// fuse_w,g,b, exp_w,g,b, ctr_w, reg_w, cls_w, cls_b, scales.
// Offset-MLP branch (5..11) and coords (0) are dead w.r.t. the output tensor.
// ---------------------------------------------------------------------------
extern "C" void kernel_launch(void* const* d_in, const int* in_sizes, int n_in,
                              void* d_out, int out_size) {
    const float* feats     = (const float*)d_in[1];
    const int*   nbr       = (const int*)  d_in[2];
    const float* Wsem      = (const float*)d_in[3];
    const float* bsem      = (const float*)d_in[4];
    const float* fo_w      = (const float*)d_in[12];
    const float* fo_g      = (const float*)d_in[13];
    const float* fo_b      = (const float*)d_in[14];
    const float* cls_out_w = (const float*)d_in[15];
    const float* cls_out_g = (const float*)d_in[16];
    const float* cls_out_b = (const float*)d_in[17];
    const float* up_w      = (const float*)d_in[18];
    const float* up_g      = (const float*)d_in[19];
    const float* up_b      = (const float*)d_in[20];
    const float* fuse_w    = (const float*)d_in[21];
    const float* fuse_g    = (const float*)d_in[22];
    const float* fuse_b    = (const float*)d_in[23];
    const float* exp_w     = (const float*)d_in[24];
    const float* exp_g     = (const float*)d_in[25];
    const float* exp_b     = (const float*)d_in[26];
    const float* ctr_w     = (const float*)d_in[27];
    const float* reg_w     = (const float*)d_in[28];
    const float* cls_w     = (const float*)d_in[29];
    const float* cls_b     = (const float*)d_in[30];
    const float* scales    = (const float*)d_in[31];
    float* out = (float*)d_out;

    const long long nelem  = (long long)out_size;
    const long long n4     = nelem >> 2;
    const long long slice4 = (n4 + G_BLOCKS - 1) / G_BLOCKS;

    k_main<<<G_BLOCKS, 256>>>(feats, nbr, Wsem, bsem,
                              fo_w, fo_g, fo_b,
                              cls_out_w, cls_out_g, cls_out_b,
                              up_w, up_g, up_b,
                              fuse_w, fuse_g, fuse_b,
                              exp_w, exp_g, exp_b,
                              ctr_w, reg_w, cls_w, cls_b, scales,
                              out, nelem, slice4);
}

// round 4
// speedup vs baseline: 1.8649x; 1.8649x over previous
#include <cuda_runtime.h>
#include <math.h>

// Problem constants (fixed by the dataset)
#define NPTS 65536
#define CH   128
#define NCLS 10
#define KNBR 27
#define OUTC 17   // 1 (ctr) + 6 (reg) + 10 (cls)

// sigmoid(s) > 0.15  <=>  s > log(0.15/0.85)
#define THRESH_LOGIT -1.7346010553881064f

#define K1_BLOCKS 4096
#define PTS_PER_B (NPTS / K1_BLOCKS)   // 16 points per block, 2 per warp

// Per-point class bitmask (bit c set <=> sigmoid(sem[p,c]) > 0.15).
// Written unconditionally every replay -> no counter, no reset, no ordering.
__device__ unsigned short g_mask[NPTS];

__device__ __forceinline__ float elu1(float x) {
    return x > 0.f ? x : (expf(x) - 1.f);
}

// ---------------------------------------------------------------------------
// K1: every block zero-fills its output slice AND computes sem for 16 points.
// Loads issued first, stores fire-and-forget, compute hides in the drain.
// ---------------------------------------------------------------------------
__global__ void __launch_bounds__(256)
k1_zero_sem(const float* __restrict__ feats,
            const float* __restrict__ Wsem,
            const float* __restrict__ bsem,
            float* __restrict__ out,
            long long n4, long long slice4) {
    __shared__ float4 sWt[NCLS * 32];   // Wsem transposed: sWt[c*32+g] = W[4g..4g+3][c]
    __shared__ float  sThr[NCLS];

    const int tid  = threadIdx.x;
    const int b    = blockIdx.x;
    const int warp = tid >> 5;
    const int lane = tid & 31;

    // ---- issue sem feats loads first (latency hidden behind the stores) ----
    const int p0 = b * PTS_PER_B + warp * 2;
    const float4 f0 = reinterpret_cast<const float4*>(feats)[(long long)p0 * 32 + lane];
    const float4 f1 = reinterpret_cast<const float4*>(feats)[(long long)(p0 + 1) * 32 + lane];

    // ---- stage weights (tiny, L2-resident after first blocks) ----
    if (tid < NCLS * 32) {
        const int c = tid >> 5, g = tid & 31;
        sWt[tid] = make_float4(Wsem[(4 * g + 0) * NCLS + c],
                               Wsem[(4 * g + 1) * NCLS + c],
                               Wsem[(4 * g + 2) * NCLS + c],
                               Wsem[(4 * g + 3) * NCLS + c]);
    }
    if (tid < NCLS) sThr[tid] = THRESH_LOGIT - bsem[tid];

    // ---- zero-fill this block's contiguous slice (fire-and-forget) ----
    {
        float4* out4 = reinterpret_cast<float4*>(out);
        const float4 z = make_float4(0.f, 0.f, 0.f, 0.f);
        long long t   = b * slice4 + tid;
        long long end = (b + 1) * slice4;
        if (end > n4) end = n4;
        for (; t < end; t += 256) out4[t] = z;
    }

    __syncthreads();

    // ---- sem for 2 points per warp ----
    float s0[NCLS], s1[NCLS];
#pragma unroll
    for (int c = 0; c < NCLS; c++) {
        const float4 w = sWt[c * 32 + lane];
        s0[c] = f0.x * w.x + f0.y * w.y + f0.z * w.z + f0.w * w.w;
        s1[c] = f1.x * w.x + f1.y * w.y + f1.z * w.z + f1.w * w.w;
    }
    // folded reduction (validated in R2): xor16 on all 10, split classes
    // across half-warps, butterfly on 5, read partner set from lane16.
#pragma unroll
    for (int c = 0; c < NCLS; c++) {
        s0[c] += __shfl_xor_sync(0xffffffffu, s0[c], 16);
        s1[c] += __shfl_xor_sync(0xffffffffu, s1[c], 16);
    }
    const bool hi = (lane >= 16);
    float a5[5], b5[5];
#pragma unroll
    for (int k = 0; k < 5; k++) {
        a5[k] = hi ? s0[k + 5] : s0[k];
        b5[k] = hi ? s1[k + 5] : s1[k];
    }
#pragma unroll
    for (int off = 8; off; off >>= 1)
#pragma unroll
        for (int k = 0; k < 5; k++) {
            a5[k] += __shfl_xor_sync(0xffffffffu, a5[k], off);
            b5[k] += __shfl_xor_sync(0xffffffffu, b5[k], off);
        }
    float ua[5], ub[5];
#pragma unroll
    for (int k = 0; k < 5; k++) {
        ua[k] = __shfl_sync(0xffffffffu, a5[k], 16);
        ub[k] = __shfl_sync(0xffffffffu, b5[k], 16);
    }
    if (lane == 0) {
        unsigned m0 = 0, m1 = 0;
#pragma unroll
        for (int k = 0; k < 5; k++) {
            if (a5[k] > sThr[k])     m0 |= 1u << k;
            if (ua[k] > sThr[k + 5]) m0 |= 1u << (k + 5);
            if (b5[k] > sThr[k])     m1 |= 1u << k;
            if (ub[k] > sThr[k + 5]) m1 |= 1u << (k + 5);
        }
        // p0 is even: one 32-bit store covers both masks
        *reinterpret_cast<unsigned*>(&g_mask[p0]) = m0 | (m1 << 16);
    }
}

// ---------------------------------------------------------------------------
// K2: scan masks (4 per thread via uint2); run head pipeline only for flagged
// (point, class) pairs. Hot path: one 8B load per thread, ballot, exit.
// 64 blocks x 256 threads; block owns 1024 points.
// ---------------------------------------------------------------------------
__global__ void k2_heads(const float* __restrict__ feats,
                         const int*   __restrict__ nbr,
                         const float* __restrict__ fo_w,
                         const float* __restrict__ fo_g,
                         const float* __restrict__ fo_b,
                         const float* __restrict__ cls_out_w,
                         const float* __restrict__ cls_out_g,
                         const float* __restrict__ cls_out_b,
                         const float* __restrict__ up_w,
                         const float* __restrict__ up_g,
                         const float* __restrict__ up_b,
                         const float* __restrict__ fuse_w,
                         const float* __restrict__ fuse_g,
                         const float* __restrict__ fuse_b,
                         const float* __restrict__ exp_w,
                         const float* __restrict__ exp_g,
                         const float* __restrict__ exp_b,
                         const float* __restrict__ ctr_w,
                         const float* __restrict__ reg_w,
                         const float* __restrict__ cls_w,
                         const float* __restrict__ cls_b,
                         const float* __restrict__ scales,
                         float* __restrict__ out) {
    __shared__ unsigned short smask[1024];
    __shared__ float sx[CH];
    __shared__ float cat[2 * CH];
    __shared__ float sec[CH];
    __shared__ float sof[CH];

    const int tid  = threadIdx.x;
    const int base = blockIdx.x * 1024;

    const uint2 v = reinterpret_cast<const uint2*>(g_mask + base)[tid];
    reinterpret_cast<uint2*>(smask)[tid] = v;
    if (!__syncthreads_or((v.x | v.y) != 0)) return;   // hot path

    const int j = tid;   // channel id where j < CH
    for (int t = 0; t < 1024; t++) {
        unsigned m = smask[t];
        if (!m) continue;
        const int i = base + t;

        // offset_features[i] = ELU(affine(sum_k feats[nbr[i,k]] @ fo_w[k]))
        float acc = 0.f;
        for (int k = 0; k < KNBR; k++) {
            const int nb = nbr[i * KNBR + k];
            __syncthreads();
            if (j < CH) sx[j] = feats[(long long)nb * CH + j];
            __syncthreads();
            if (j < CH) {
                const float* W = fo_w + (long long)k * CH * CH;
                for (int mm = 0; mm < CH; mm++) acc += sx[mm] * W[mm * CH + j];
            }
        }
        if (j < CH) sof[j] = elu1(acc * fo_g[j] + fo_b[j]);

        while (m) {
            const int c = __ffs(m) - 1;
            m &= (m - 1);
            for (int half = 0; half < 2; half++) {
                __syncthreads();
                if (j < CH) sx[j] = (half == 0) ? sof[j] : feats[(long long)i * CH + j];
                __syncthreads();
                if (j < CH) {   // hc
                    const float* W = cls_out_w + (long long)c * CH * CH;
                    float a = 0.f;
                    for (int mm = 0; mm < CH; mm++) a += sx[mm] * W[mm * CH + j];
                    a = a * cls_out_g[c * CH + j] + cls_out_b[c * CH + j];
                    cat[j] = elu1(a);
                }
                __syncthreads();
                if (j < CH) {   // uc
                    const float* W = up_w + (long long)c * CH * CH;
                    float a = 0.f;
                    for (int mm = 0; mm < CH; mm++) a += cat[mm] * W[mm * CH + j];
                    a = a * up_g[c * CH + j] + up_b[c * CH + j];
                    cat[CH + j] = elu1(a);
                }
                __syncthreads();
                float fc = 0.f;
                if (j < CH) {   // fc
                    const float* W = fuse_w + (long long)c * 2 * CH * CH;
                    float a = 0.f;
                    for (int mm = 0; mm < 2 * CH; mm++) a += cat[mm] * W[mm * CH + j];
                    a = a * fuse_g[c * CH + j] + fuse_b[c * CH + j];
                    fc = elu1(a);
                }
                __syncthreads();
                if (j < CH) sx[j] = fc;
                __syncthreads();
                if (j < CH) {   // ec
                    const float* W = exp_w + (long long)c * CH * CH;
                    float a = 0.f;
                    for (int mm = 0; mm < CH; mm++) a += sx[mm] * W[mm * CH + j];
                    a = a * exp_g[c * CH + j] + exp_b[c * CH + j];
                    sec[j] = elu1(a);
                }
                __syncthreads();

                const long long row = (half == 0) ? (long long)i : (long long)(NPTS + i);
                float* orow = out + ((long long)c * 2 * NPTS + row) * OUTC;
                if (j == 0) {
                    float s = 0.f;
                    for (int mm = 0; mm < CH; mm++) s += sec[mm] * ctr_w[mm];
                    orow[0] = s;
                } else if (j < 7) {
                    const int r = j - 1;
                    float s = 0.f;
                    for (int mm = 0; mm < CH; mm++) s += sec[mm] * reg_w[mm * 6 + r];
                    orow[j] = expf(scales[c] * s);
                } else if (j < 17) {
                    const int q = j - 7;
                    float s = 0.f;
                    for (int mm = 0; mm < CH; mm++) s += sec[mm] * cls_w[mm * NCLS + q];
                    orow[j] = s + cls_b[q];
                }
            }
        }
    }
}

// ---------------------------------------------------------------------------
// Launch. Input order per metadata: coords, feats, nbr, Wsem, bsem,
// off_w1,g1,b1, off_w2,g2,b2, off_w3, fo_w,g,b, cls_out_w,g,b, up_w,g,b,
// fuse_w,g,b, exp_w,g,b, ctr_w, reg_w, cls_w, cls_b, scales.
// Offset-MLP branch (5..11) and coords (0) are dead w.r.t. the output tensor.
// ---------------------------------------------------------------------------
extern "C" void kernel_launch(void* const* d_in, const int* in_sizes, int n_in,
                              void* d_out, int out_size) {
    const float* feats     = (const float*)d_in[1];
    const int*   nbr       = (const int*)  d_in[2];
    const float* Wsem      = (const float*)d_in[3];
    const float* bsem      = (const float*)d_in[4];
    const float* fo_w      = (const float*)d_in[12];
    const float* fo_g      = (const float*)d_in[13];
    const float* fo_b      = (const float*)d_in[14];
    const float* cls_out_w = (const float*)d_in[15];
    const float* cls_out_g = (const float*)d_in[16];
    const float* cls_out_b = (const float*)d_in[17];
    const float* up_w      = (const float*)d_in[18];
    const float* up_g      = (const float*)d_in[19];
    const float* up_b      = (const float*)d_in[20];
    const float* fuse_w    = (const float*)d_in[21];
    const float* fuse_g    = (const float*)d_in[22];
    const float* fuse_b    = (const float*)d_in[23];
    const float* exp_w     = (const float*)d_in[24];
    const float* exp_g     = (const float*)d_in[25];
    const float* exp_b     = (const float*)d_in[26];
    const float* ctr_w     = (const float*)d_in[27];
    const float* reg_w     = (const float*)d_in[28];
    const float* cls_w     = (const float*)d_in[29];
    const float* cls_b     = (const float*)d_in[30];
    const float* scales    = (const float*)d_in[31];
    float* out = (float*)d_out;

    const long long nelem  = (long long)out_size;
    const long long n4     = nelem >> 2;                         // exact: nelem % 4 == 0
    const long long slice4 = (n4 + K1_BLOCKS - 1) / K1_BLOCKS;

    k1_zero_sem<<<K1_BLOCKS, 256>>>(feats, Wsem, bsem, out, n4, slice4);

    k2_heads<<<NPTS / 1024, 256>>>(feats, nbr, fo_w, fo_g, fo_b,
                                   cls_out_w, cls_out_g, cls_out_b,
                                   up_w, up_g, up_b,
                                   fuse_w, fuse_g, fuse_b,
                                   exp_w, exp_g, exp_b,
                                   ctr_w, reg_w, cls_w, cls_b, scales, out);
}